// round 15
// baseline (speedup 1.0000x reference)
#include <cuda_runtime.h>
#include <math.h>

#define BB 4
#define NN 300
#define CC 80
#define MM 24
#define CF 128
#define HF 64
#define HM 224
#define TT 28

#define S_IMG 896.0f
#define CENTER_R 44.8f
#define EPSF 1e-8f

#define PROJ_BLKS  128                      // 4 img * 16 chunks * 2 class-groups(12)
#define COL_BLKS   (BB*MM)                  // 96
#define NEG_BLKS   75                       // 75*1280 = 96000
#define K1_GRID    (PROJ_BLKS+COL_BLKS+NEG_BLKS)   // 299
#define K2_GRID    (BB*MM*2)                // 192: block per (b, j, half)

// ---------------- scratch ----------------
__device__ float  g_proj[BB*MM*HF*HF];
__device__ float  g_costT[BB*NN*MM];
__device__ unsigned char g_matchT[BB*NN*MM];
__device__ int    g_valid[BB*NN];
__device__ float  g_gcrop[BB*MM*TT*TT];
__device__ float  g_gsum[BB*MM];
__device__ double g_accb[32][5] = {};
__device__ int    g_done = 0;

// ---------------- helpers ----------------
__device__ __forceinline__ float sigm(float x){ return 1.f/(1.f+expf(-x)); }

__device__ __forceinline__ float iou_exact(float ax1,float ay1,float ax2,float ay2,
                                           float bx1,float by1,float bx2,float by2){
    float ltx=fmaxf(ax1,bx1), lty=fmaxf(ay1,by1);
    float rbx=fminf(ax2,bx2), rby=fminf(ay2,by2);
    float w=fmaxf(__fsub_rn(rbx,ltx),0.f), h=fmaxf(__fsub_rn(rby,lty),0.f);
    float inter=__fmul_rn(w,h);
    float aA=__fmul_rn(fmaxf(__fsub_rn(ax2,ax1),0.f), fmaxf(__fsub_rn(ay2,ay1),0.f));
    float aB=__fmul_rn(fmaxf(__fsub_rn(bx2,bx1),0.f), fmaxf(__fsub_rn(by2,by1),0.f));
    float uni=__fsub_rn(__fadd_rn(aA,aB), inter);
    return __fdiv_rn(inter, __fadd_rn(uni, EPSF));
}

__device__ __forceinline__ float giou_pair(float a0,float a1,float a2,float a3,
                                           float g0,float g1,float g2,float g3){
    float ltx=fmaxf(a0,g0), lty=fmaxf(a1,g1);
    float rbx=fminf(a2,g2), rby=fminf(a3,g3);
    float w=fmaxf(rbx-ltx,0.f), h=fmaxf(rby-lty,0.f);
    float inter=w*h;
    float aA=fmaxf(a2-a0,0.f)*fmaxf(a3-a1,0.f);
    float aB=fmaxf(g2-g0,0.f)*fmaxf(g3-g1,0.f);
    float uni=aA+aB-inter;
    float iou=inter/(uni+EPSF);
    float ex=fminf(a0,g0), ey=fminf(a1,g1);
    float fx=fmaxf(a2,g2), fy=fmaxf(a3,g3);
    float enc=fmaxf(fx-ex,0.f)*fmaxf(fy-ey,0.f);
    return iou-(enc-uni)/(enc+EPSF);
}

__device__ __forceinline__ float bilerp(const float* __restrict__ img,int W,int H,float X,float Y){
    float x0f=fminf(fmaxf(floorf(X),0.f),(float)(W-1));
    float y0f=fminf(fmaxf(floorf(Y),0.f),(float)(H-1));
    float wx=fminf(fmaxf(X-x0f,0.f),1.f);
    float wy=fminf(fmaxf(Y-y0f,0.f),1.f);
    int x0=(int)x0f, y0=(int)y0f;
    int x1=min(x0+1,W-1), y1=min(y0+1,H-1);
    float g00=__ldg(&img[y0*W+x0]), g01=__ldg(&img[y0*W+x1]);
    float g10=__ldg(&img[y1*W+x0]), g11=__ldg(&img[y1*W+x1]);
    return g00*(1.f-wx)*(1.f-wy)+g01*wx*(1.f-wy)+g10*(1.f-wx)*wy+g11*wx*wy;
}

// ================= K1: proj (register-buffered) || columns || neg focal =================
__global__ void __launch_bounds__(256)
k_stage1(const float* __restrict__ logits, const float* __restrict__ boxes,
         const float* __restrict__ feat,   const float* __restrict__ wmask,
         const int*   __restrict__ gcls,   const float* __restrict__ gbox,
         const float* __restrict__ gmask){
    int blk=blockIdx.x, tid=threadIdx.x;
    int lane=tid&31, warp=tid>>5;
    int bank=blk&31;

    if(blk < PROJ_BLKS){
        // ---- projected class maps: 12 classes per block, register-buffered loads ----
        __shared__ float wm[12*CF];
        int b=blk/32;
        int r=blk%32;
        int chunk=r>>1;
        int jg=r&1;
        int px0=chunk*256;
        for(int idx=tid; idx<12*CF; idx+=256){
            int j=jg*12+idx/CF, f=idx%CF;
            wm[idx]=wmask[gcls[b*MM+j]*CF+f];
        }
        __syncthreads();
        float acc[12];
        #pragma unroll
        for(int j=0;j<12;j++) acc[j]=0.f;
        const float* fb = feat + ((size_t)b*CF)*(HF*HF) + px0 + tid;
        for(int fc=0; fc<8; fc++){
            float v[16];
            #pragma unroll
            for(int k=0;k<16;k++)
                v[k]=__ldg(&fb[(size_t)(fc*16+k)*(HF*HF)]);
            #pragma unroll
            for(int k=0;k<16;k++){
                const float* w0=&wm[fc*16+k];
                #pragma unroll
                for(int j=0;j<12;j++) acc[j] += v[k]*w0[j*CF];
            }
        }
        #pragma unroll
        for(int j=0;j<12;j++) g_proj[((b*MM+jg*12+j)*(HF*HF))+px0+tid]=acc[j];
        return;
    }

    if(blk < PROJ_BLKS+COL_BLKS){
        int idx=blk-PROJ_BLKS;
        int b=idx/MM, j=idx%MM;
        __shared__ float col[NN];
        __shared__ unsigned char sval[NN];
        __shared__ float sg[MM][4];
        __shared__ float wtop[8][10];
        __shared__ int   s_dk;
        __shared__ double sred[8];
        if(tid<MM){
            sg[tid][0]=gbox[(b*MM+tid)*4+0]; sg[tid][1]=gbox[(b*MM+tid)*4+1];
            sg[tid][2]=gbox[(b*MM+tid)*4+2]; sg[tid][3]=gbox[(b*MM+tid)*4+3];
        }
        __syncthreads();
        float gx1=sg[j][0],gy1=sg[j][1],gx2=sg[j][2],gy2=sg[j][3];
        float gcx=(gx1+gx2)*0.5f, gcy=(gy1+gy2)*0.5f;
        int cls_j=gcls[b*MM+j];
        float ng0=gx1/S_IMG,ng1=gy1/S_IMG,ng2=gx2/S_IMG,ng3=gy2/S_IMG;
        float loc[10];
        #pragma unroll
        for(int k=0;k<10;k++) loc[k]=-1e30f;
        #pragma unroll 2
        for(int i=tid;i<NN;i+=256){
            const float* bx=&boxes[(size_t)(b*NN+i)*4];
            float ax1=bx[0],ay1=bx[1],ax2=bx[2],ay2=bx[3];
            float cx=(ax1+ax2)*0.5f, cy=(ay1+ay2)*0.5f;
            int any=0;
            #pragma unroll 4
            for(int q=0;q<MM;q++){
                float qx1=sg[q][0],qy1=sg[q][1],qx2=sg[q][2],qy2=sg[q][3];
                bool igt=(cx>=qx1)&&(cx<=qx2)&&(cy>=qy1)&&(cy<=qy2);
                bool ict=(fabsf(cx-(qx1+qx2)*0.5f)<=CENTER_R)&&(fabsf(cy-(qy1+qy2)*0.5f)<=CENTER_R);
                any |= (igt||ict);
            }
            sval[i]=(unsigned char)any;
            g_valid[b*NN+i]=any;
            float x=logits[(size_t)(b*NN+i)*CC + cls_j];
            float p=sigm(x);
            float neg=-logf(1.f-p+EPSF)*0.75f*p*p;
            float pos=-logf(p+EPSF)*0.25f*(1.f-p)*(1.f-p);
            float cls_cost=2.f*(pos-neg);
            float na0=ax1/S_IMG,na1=ay1/S_IMG,na2=ax2/S_IMG,na3=ay2/S_IMG;
            float l1c=5.f*(fabsf(na0-ng0)+fabsf(na1-ng1)+fabsf(na2-ng2)+fabsf(na3-ng3));
            float ngiou=giou_pair(na0,na1,na2,na3,ng0,ng1,ng2,ng3);
            bool ingt=(cx>=gx1)&&(cx<=gx2)&&(cy>=gy1)&&(cy<=gy2);
            bool inct=(fabsf(cx-gcx)<=CENTER_R)&&(fabsf(cy-gcy)<=CENTER_R);
            float cost=cls_cost+l1c+2.f*(1.f-ngiou);
            cost += (ingt&&inct)?0.f:1e5f;
            cost += any?0.f:1e9f;
            col[i]=cost;
            g_costT[(size_t)(b*NN+i)*MM+j]=cost;
            float iou=iou_exact(ax1,ay1,ax2,ay2,gx1,gy1,gx2,gy2);
            float v=any? iou : 0.f;
            if(v>loc[9]){
                int k=9;
                #pragma unroll
                for(int q=9;q>0;q--){
                    if(loc[q-1]<v){ loc[q]=loc[q-1]; k=q-1; } else break;
                }
                loc[k]=v;
            }
        }
        {
            int p=0; float out10[10];
            #pragma unroll
            for(int r=0;r<10;r++){
                float h=(p<10)?loc[p]:-1e30f;
                float m=h;
                #pragma unroll
                for(int off=16;off;off>>=1)
                    m=fmaxf(m,__shfl_xor_sync(0xffffffffu,m,off));
                out10[r]=m;
                unsigned ball=__ballot_sync(0xffffffffu, h==m);
                if(lane==(__ffs(ball)-1)) p++;
            }
            if(lane==0){
                #pragma unroll
                for(int r=0;r<10;r++) wtop[warp][r]=out10[r];
            }
        }
        __syncthreads();
        if(warp==0){
            int p=0; float s=0.f;
            #pragma unroll
            for(int r=0;r<10;r++){
                float h=(lane<8 && p<10)? wtop[lane][p] : -1e30f;
                float m=h;
                #pragma unroll
                for(int off=16;off;off>>=1)
                    m=fmaxf(m,__shfl_xor_sync(0xffffffffu,m,off));
                s+=m;
                unsigned ball=__ballot_sync(0xffffffffu, h==m && lane<8);
                if(lane==(__ffs(ball)-1)) p++;
            }
            if(lane==0){
                int dk=(int)s;
                if(dk<1)dk=1; if(dk>NN)dk=NN;
                s_dk=dk;
            }
        }
        __syncthreads();
        int dk=s_dk;
        #pragma unroll 2
        for(int i=tid;i<NN;i+=256){
            float myc=col[i];
            int r=0;
            #pragma unroll 4
            for(int k=0;k<NN;k++){
                float ck=col[k];
                r += (ck<myc) || (ck==myc && k<i);
            }
            g_matchT[(size_t)(b*NN+i)*MM+j]=(unsigned char)((r<dk) && sval[i]);
        }
        {
            const float* gm=&gmask[(size_t)(b*MM+j)*(HM*HM)];
            float qx1=gx1*0.25f, qy1=gy1*0.25f, qx2=gx2*0.25f, qy2=gy2*0.25f;
            float gs=0.f;
            #pragma unroll
            for(int k=0;k<4;k++){
                int pix=tid+k*256;
                if(pix<TT*TT){
                    int ty=pix/TT, tx=pix%TT;
                    float ux=((float)tx+0.5f)/28.f, uy=((float)ty+0.5f)/28.f;
                    float Xg=qx1+(qx2-qx1)*ux-0.5f, Yg=qy1+(qy2-qy1)*uy-0.5f;
                    float gv=bilerp(gm,HM,HM,Xg,Yg);
                    g_gcrop[(size_t)(b*MM+j)*(TT*TT)+pix]=gv;
                    gs+=gv;
                }
            }
            #pragma unroll
            for(int off=16;off;off>>=1) gs+=__shfl_down_sync(0xffffffffu,gs,off);
            if(lane==0) sred[warp]=(double)gs;
            __syncthreads();
            if(tid==0){
                double t=0;
                #pragma unroll
                for(int w=0;w<8;w++) t+=sred[w];
                g_gsum[b*MM+j]=(float)t;
            }
        }
        return;
    }

    // ---- negative-class focal bulk ----
    {
        __shared__ double sred2[8];
        int base=(blk-PROJ_BLKS-COL_BLKS)*1280 + tid;
        double cl=0.0;
        #pragma unroll
        for(int k=0;k<5;k++){
            int e=base+k*256;
            float x=logits[e];
            float p=1.f/(1.f+__expf(-x));
            float sp=fmaxf(x,0.f)+log1pf(__expf(-fabsf(x)));
            cl += (double)(0.75f*p*p*sp);
        }
        #pragma unroll
        for(int off=16;off;off>>=1) cl+=__shfl_down_sync(0xffffffffu,cl,off);
        if(lane==0) sred2[warp]=cl;
        __syncthreads();
        if(tid==0){
            double a=0;
            #pragma unroll
            for(int w=0;w<8;w++) a+=sred2[w];
            atomicAdd(&g_accb[bank][0],a);
        }
    }
}

// ================= K2: assignment-first, conditional staging, smem dice =================
__global__ void __launch_bounds__(256)
k_stage2(const float* __restrict__ logits, const float* __restrict__ boxes,
         const int* __restrict__ gcls, const float* __restrict__ gbox,
         float* __restrict__ out){
    int blk=blockIdx.x, tid=threadIdx.x;
    int lane=tid&31, warp=tid>>5;
    int bank=blk&31;
    int b=blk/(MM*2);
    int rem=blk%(MM*2);
    int j=rem>>1;
    int half=rem&1;

    __shared__ float pjs[HF*HF];    // 16 KB
    __shared__ float gcs[TT*TT];    // ~3 KB
    __shared__ int   lst[NN];
    __shared__ int   s_cnt;
    __shared__ float swy[8][TT];
    __shared__ int   sr0[8][TT], sr1[8][TT];
    if(tid==0) s_cnt=0;
    __syncthreads();

    // inline assignment FIRST: thread t handles proposal i=2t+half; vectorized row loads
    {
        int t=tid;
        int i=2*t+half;
        if(t<150 && g_valid[b*NN+i]){
            const float4* c4=(const float4*)&g_costT[(size_t)(b*NN+i)*MM];
            float4 ca=__ldg(&c4[0]), cb=__ldg(&c4[1]), cc2=__ldg(&c4[2]);
            float4 cd=__ldg(&c4[3]), ce=__ldg(&c4[4]), cf=__ldg(&c4[5]);
            const unsigned* m4=(const unsigned*)&g_matchT[(size_t)(b*NN+i)*MM];
            unsigned mw[6];
            #pragma unroll
            for(int k=0;k<6;k++) mw[k]=__ldg(&m4[k]);
            float cv[24]={ca.x,ca.y,ca.z,ca.w, cb.x,cb.y,cb.z,cb.w,
                          cc2.x,cc2.y,cc2.z,cc2.w, cd.x,cd.y,cd.z,cd.w,
                          ce.x,ce.y,ce.z,ce.w, cf.x,cf.y,cf.z,cf.w};
            float bv=cv[0]; int bi=0;
            #pragma unroll
            for(int q=1;q<MM;q++){ if(cv[q]<bv){bv=cv[q];bi=q;} }
            int cnt=0, first=-1;
            #pragma unroll
            for(int k=0;k<6;k++){
                unsigned v=__vcmpne4(mw[k],0u);
                cnt += __popc(v)>>3;
                if(first<0 && v) first=k*4 + ((__ffs(v)-1)>>3);
            }
            int ji=(cnt==1)? first : bi;
            if(ji==j){ int p=atomicAdd(&s_cnt,1); lst[p]=i; }
        }
    }
    __syncthreads();
    int cnt=s_cnt;

    if(cnt>0){
        // stage proj map + gcrop into smem (coalesced) only when needed
        {
            const float* pj=&g_proj[(size_t)(b*MM+j)*(HF*HF)];
            #pragma unroll
            for(int k=0;k<16;k++) pjs[k*256+tid]=pj[k*256+tid];
            const float* gc=&g_gcrop[(size_t)(b*MM+j)*(TT*TT)];
            #pragma unroll
            for(int k=0;k<4;k++){
                int p=tid+k*256;
                if(p<TT*TT) gcs[p]=gc[p];
            }
        }
        __syncthreads();

        // warp per proposal; coords hoisted (registers for cols, smem for rows)
        for(int idx=warp; idx<cnt; idx+=8){
            int i=lst[idx];
            const float* bx=&boxes[(size_t)(b*NN+i)*4];
            const float FS=(float)(64.0/896.0);
            float px1=bx[0]*FS, py1=bx[1]*FS, px2=bx[2]*FS, py2=bx[3]*FS;

            float u=((float)lane+0.5f)*(1.f/28.f);
            float X=px1+(px2-px1)*u-0.5f;
            float x0f=fminf(fmaxf(floorf(X),0.f),63.f);
            float wx=fminf(fmaxf(X-x0f,0.f),1.f);
            int x0=(int)x0f;
            int x1=min(x0+1,63);
            float Y=py1+(py2-py1)*u-0.5f;
            float y0f=fminf(fmaxf(floorf(Y),0.f),63.f);
            float wyv=fminf(fmaxf(Y-y0f,0.f),1.f);
            int r0=((int)y0f)*HF;
            int r1=min((int)y0f+1,63)*HF;
            if(lane<TT){ swy[warp][lane]=wyv; sr0[warp][lane]=r0; sr1[warp][lane]=r1; }
            __syncwarp();

            float inter=0.f, sm=0.f;
            #pragma unroll
            for(int r=0;r<TT;r++){
                float wyr=swy[warp][r];
                int ro0=sr0[warp][r], ro1=sr1[warp][r];
                if(lane<TT){
                    float g00=pjs[ro0+x0], g01=pjs[ro0+x1];
                    float g10=pjs[ro1+x0], g11=pjs[ro1+x1];
                    float top=g00+wx*(g01-g00);
                    float bot=g10+wx*(g11-g10);
                    float z=top+wyr*(bot-top);
                    float mv=__fdividef(1.f, 1.f+__expf(-z));
                    inter+=mv*gcs[r*TT+lane]; sm+=mv;
                }
            }
            __syncwarp();
            #pragma unroll
            for(int off=16;off;off>>=1){
                inter+=__shfl_down_sync(0xffffffffu,inter,off);
                sm   +=__shfl_down_sync(0xffffffffu,sm,off);
            }
            if(lane==0){
                float sgv=g_gsum[b*MM+j];
                double dice=(double)(1.f-2.f*inter/(sm+sgv+EPSF));
                const float* gb=&gbox[(size_t)(b*MM+j)*4];
                float na0=bx[0]/S_IMG,na1=bx[1]/S_IMG,na2=bx[2]/S_IMG,na3=bx[3]/S_IMG;
                float ng0=gb[0]/S_IMG,ng1=gb[1]/S_IMG,ng2=gb[2]/S_IMG,ng3=gb[3]/S_IMG;
                double l1=(double)(fabsf(na0-ng0)+fabsf(na1-ng1)+fabsf(na2-ng2)+fabsf(na3-ng3));
                double gl=(double)(1.f-giou_pair(na0,na1,na2,na3,ng0,ng1,ng2,ng3));
                int mcls=gcls[b*MM+j];
                float x=logits[(size_t)(b*NN+i)*CC+mcls];
                float p=1.f/(1.f+expf(-x));
                float sp=fmaxf(x,0.f)+log1pf(expf(-fabsf(x)));
                float posv=0.25f*(1.f-p)*(1.f-p)*(sp-x);
                float negv=0.75f*p*p*sp;
                atomicAdd(&g_accb[bank][0],(double)(posv-negv));
                atomicAdd(&g_accb[bank][1],l1);
                atomicAdd(&g_accb[bank][2],gl);
                atomicAdd(&g_accb[bank][3],dice);
                atomicAdd(&g_accb[bank][4],1.0);
            }
        }
    }

    // ---- ticket: last finished block finalizes + resets ----
    __syncthreads();
    __threadfence();
    if(tid==0){
        int t=atomicAdd(&g_done,1);
        if(t==(int)gridDim.x-1){
            __threadfence();
            double a0=0,a1=0,a2=0,a3=0,a4=0;
            #pragma unroll
            for(int k=0;k<32;k++){
                a0+=g_accb[k][0]; a1+=g_accb[k][1]; a2+=g_accb[k][2];
                a3+=g_accb[k][3]; a4+=g_accb[k][4];
                g_accb[k][0]=0.0; g_accb[k][1]=0.0; g_accb[k][2]=0.0;
                g_accb[k][3]=0.0; g_accb[k][4]=0.0;
            }
            out[0]=(float)(2.0*a0/a4);
            out[1]=(float)(5.0*a1/a4);
            out[2]=(float)(2.0*a2/a4);
            out[3]=(float)(5.0*a3/a4);
            g_done=0;
        }
    }
}

extern "C" void kernel_launch(void* const* d_in, const int* in_sizes, int n_in,
                              void* d_out, int out_size){
    const float* logits=(const float*)d_in[0];
    const float* boxes =(const float*)d_in[1];
    const float* feat  =(const float*)d_in[2];
    const float* wmask =(const float*)d_in[3];
    const int*   gcls  =(const int*)  d_in[4];
    const float* gbox  =(const float*)d_in[5];
    const float* gmask =(const float*)d_in[6];
    float* out=(float*)d_out;

    k_stage1<<<K1_GRID,256>>>(logits,boxes,feat,wmask,gcls,gbox,gmask);
    k_stage2<<<K2_GRID,256>>>(logits,boxes,gcls,gbox,out);
}

// round 16
// speedup vs baseline: 1.0142x; 1.0142x over previous
#include <cuda_runtime.h>
#include <math.h>

#define BB 4
#define NN 300
#define CC 80
#define MM 24
#define CF 128
#define HF 64
#define HM 224
#define TT 28

#define S_IMG 896.0f
#define CENTER_R 44.8f
#define EPSF 1e-8f

#define PROJ_BLKS  128                      // 4 img * 16 chunks * 2 class-groups(12)
#define COL_BLKS   (BB*MM)                  // 96
#define NEG_BLKS   75                       // 75*1280 = 96000
#define K1_GRID    (PROJ_BLKS+COL_BLKS+NEG_BLKS)   // 299
#define K2_GRID    (BB*MM*2)                // 192: block per (b, j, half)

// ---------------- scratch ----------------
__device__ float  g_proj[BB*MM*HF*HF];
__device__ int    g_valid[BB*NN];
__device__ unsigned long long g_amax[BB*NN] = {};   // ~min-key (argmin via atomicMax)
__device__ unsigned g_mcnt[BB*NN] = {};             // match count
__device__ unsigned g_mfirst[BB*NN] = {};           // MM - first_matched_j (0 = none)
__device__ float  g_gcrop[BB*MM*TT*TT];
__device__ float  g_gsum[BB*MM];
__device__ double g_accb[32][5] = {};
__device__ int    g_done = 0;

// ---------------- helpers ----------------
__device__ __forceinline__ float sigm(float x){ return 1.f/(1.f+expf(-x)); }

__device__ __forceinline__ float iou_exact(float ax1,float ay1,float ax2,float ay2,
                                           float bx1,float by1,float bx2,float by2){
    float ltx=fmaxf(ax1,bx1), lty=fmaxf(ay1,by1);
    float rbx=fminf(ax2,bx2), rby=fminf(ay2,by2);
    float w=fmaxf(__fsub_rn(rbx,ltx),0.f), h=fmaxf(__fsub_rn(rby,lty),0.f);
    float inter=__fmul_rn(w,h);
    float aA=__fmul_rn(fmaxf(__fsub_rn(ax2,ax1),0.f), fmaxf(__fsub_rn(ay2,ay1),0.f));
    float aB=__fmul_rn(fmaxf(__fsub_rn(bx2,bx1),0.f), fmaxf(__fsub_rn(by2,by1),0.f));
    float uni=__fsub_rn(__fadd_rn(aA,aB), inter);
    return __fdiv_rn(inter, __fadd_rn(uni, EPSF));
}

__device__ __forceinline__ float giou_pair(float a0,float a1,float a2,float a3,
                                           float g0,float g1,float g2,float g3){
    float ltx=fmaxf(a0,g0), lty=fmaxf(a1,g1);
    float rbx=fminf(a2,g2), rby=fminf(a3,g3);
    float w=fmaxf(rbx-ltx,0.f), h=fmaxf(rby-lty,0.f);
    float inter=w*h;
    float aA=fmaxf(a2-a0,0.f)*fmaxf(a3-a1,0.f);
    float aB=fmaxf(g2-g0,0.f)*fmaxf(g3-g1,0.f);
    float uni=aA+aB-inter;
    float iou=inter/(uni+EPSF);
    float ex=fminf(a0,g0), ey=fminf(a1,g1);
    float fx=fmaxf(a2,g2), fy=fmaxf(a3,g3);
    float enc=fmaxf(fx-ex,0.f)*fmaxf(fy-ey,0.f);
    return iou-(enc-uni)/(enc+EPSF);
}

__device__ __forceinline__ float bilerp(const float* __restrict__ img,int W,int H,float X,float Y){
    float x0f=fminf(fmaxf(floorf(X),0.f),(float)(W-1));
    float y0f=fminf(fmaxf(floorf(Y),0.f),(float)(H-1));
    float wx=fminf(fmaxf(X-x0f,0.f),1.f);
    float wy=fminf(fmaxf(Y-y0f,0.f),1.f);
    int x0=(int)x0f, y0=(int)y0f;
    int x1=min(x0+1,W-1), y1=min(y0+1,H-1);
    float g00=__ldg(&img[y0*W+x0]), g01=__ldg(&img[y0*W+x1]);
    float g10=__ldg(&img[y1*W+x0]), g11=__ldg(&img[y1*W+x1]);
    return g00*(1.f-wx)*(1.f-wy)+g01*wx*(1.f-wy)+g10*(1.f-wx)*wy+g11*wx*wy;
}

// ordered-uint encoding: strictly monotonic with float order
__device__ __forceinline__ unsigned float_ord(float f){
    unsigned u=__float_as_uint(f);
    return (u&0x80000000u)? ~u : (u|0x80000000u);
}

// ================= K1: proj (register-buffered) || columns || neg focal =================
__global__ void __launch_bounds__(256)
k_stage1(const float* __restrict__ logits, const float* __restrict__ boxes,
         const float* __restrict__ feat,   const float* __restrict__ wmask,
         const int*   __restrict__ gcls,   const float* __restrict__ gbox,
         const float* __restrict__ gmask){
    int blk=blockIdx.x, tid=threadIdx.x;
    int lane=tid&31, warp=tid>>5;
    int bank=blk&31;

    if(blk < PROJ_BLKS){
        __shared__ float wm[12*CF];
        int b=blk/32;
        int r=blk%32;
        int chunk=r>>1;
        int jg=r&1;
        int px0=chunk*256;
        for(int idx=tid; idx<12*CF; idx+=256){
            int j=jg*12+idx/CF, f=idx%CF;
            wm[idx]=wmask[gcls[b*MM+j]*CF+f];
        }
        __syncthreads();
        float acc[12];
        #pragma unroll
        for(int j=0;j<12;j++) acc[j]=0.f;
        const float* fb = feat + ((size_t)b*CF)*(HF*HF) + px0 + tid;
        for(int fc=0; fc<8; fc++){
            float v[16];
            #pragma unroll
            for(int k=0;k<16;k++)
                v[k]=__ldg(&fb[(size_t)(fc*16+k)*(HF*HF)]);
            #pragma unroll
            for(int k=0;k<16;k++){
                const float* w0=&wm[fc*16+k];
                #pragma unroll
                for(int j=0;j<12;j++) acc[j] += v[k]*w0[j*CF];
            }
        }
        #pragma unroll
        for(int j=0;j<12;j++) g_proj[((b*MM+jg*12+j)*(HF*HF))+px0+tid]=acc[j];
        return;
    }

    if(blk < PROJ_BLKS+COL_BLKS){
        int idx=blk-PROJ_BLKS;
        int b=idx/MM, j=idx%MM;
        __shared__ float col[NN];
        __shared__ unsigned char sval[NN];
        __shared__ float sg[MM][4];
        __shared__ float wtop[8][10];
        __shared__ int   s_dk;
        __shared__ double sred[8];
        if(tid<MM){
            sg[tid][0]=gbox[(b*MM+tid)*4+0]; sg[tid][1]=gbox[(b*MM+tid)*4+1];
            sg[tid][2]=gbox[(b*MM+tid)*4+2]; sg[tid][3]=gbox[(b*MM+tid)*4+3];
        }
        __syncthreads();
        float gx1=sg[j][0],gy1=sg[j][1],gx2=sg[j][2],gy2=sg[j][3];
        float gcx=(gx1+gx2)*0.5f, gcy=(gy1+gy2)*0.5f;
        int cls_j=gcls[b*MM+j];
        float ng0=gx1/S_IMG,ng1=gy1/S_IMG,ng2=gx2/S_IMG,ng3=gy2/S_IMG;
        float loc[10];
        #pragma unroll
        for(int k=0;k<10;k++) loc[k]=-1e30f;
        #pragma unroll 2
        for(int i=tid;i<NN;i+=256){
            const float* bx=&boxes[(size_t)(b*NN+i)*4];
            float ax1=bx[0],ay1=bx[1],ax2=bx[2],ay2=bx[3];
            float cx=(ax1+ax2)*0.5f, cy=(ay1+ay2)*0.5f;
            int any=0;
            #pragma unroll 4
            for(int q=0;q<MM;q++){
                float qx1=sg[q][0],qy1=sg[q][1],qx2=sg[q][2],qy2=sg[q][3];
                bool igt=(cx>=qx1)&&(cx<=qx2)&&(cy>=qy1)&&(cy<=qy2);
                bool ict=(fabsf(cx-(qx1+qx2)*0.5f)<=CENTER_R)&&(fabsf(cy-(qy1+qy2)*0.5f)<=CENTER_R);
                any |= (igt||ict);
            }
            sval[i]=(unsigned char)any;
            g_valid[b*NN+i]=any;
            float x=logits[(size_t)(b*NN+i)*CC + cls_j];
            float p=sigm(x);
            float neg=-logf(1.f-p+EPSF)*0.75f*p*p;
            float pos=-logf(p+EPSF)*0.25f*(1.f-p)*(1.f-p);
            float cls_cost=2.f*(pos-neg);
            float na0=ax1/S_IMG,na1=ay1/S_IMG,na2=ax2/S_IMG,na3=ay2/S_IMG;
            float l1c=5.f*(fabsf(na0-ng0)+fabsf(na1-ng1)+fabsf(na2-ng2)+fabsf(na3-ng3));
            float ngiou=giou_pair(na0,na1,na2,na3,ng0,ng1,ng2,ng3);
            bool ingt=(cx>=gx1)&&(cx<=gx2)&&(cy>=gy1)&&(cy<=gy2);
            bool inct=(fabsf(cx-gcx)<=CENTER_R)&&(fabsf(cy-gcy)<=CENTER_R);
            float cost=cls_cost+l1c+2.f*(1.f-ngiou);
            cost += (ingt&&inct)?0.f:1e5f;
            cost += any?0.f:1e9f;
            col[i]=cost;
            // argmin via atomicMax of ~key (key = ordered(cost)<<32 | j)
            if(any){
                unsigned long long key=(((unsigned long long)float_ord(cost))<<32)|(unsigned)j;
                atomicMax(&g_amax[b*NN+i], ~key);
            }
            float iou=iou_exact(ax1,ay1,ax2,ay2,gx1,gy1,gx2,gy2);
            float v=any? iou : 0.f;
            if(v>loc[9]){
                int k=9;
                #pragma unroll
                for(int q=9;q>0;q--){
                    if(loc[q-1]<v){ loc[q]=loc[q-1]; k=q-1; } else break;
                }
                loc[k]=v;
            }
        }
        {
            int p=0; float out10[10];
            #pragma unroll
            for(int r=0;r<10;r++){
                float h=(p<10)?loc[p]:-1e30f;
                float m=h;
                #pragma unroll
                for(int off=16;off;off>>=1)
                    m=fmaxf(m,__shfl_xor_sync(0xffffffffu,m,off));
                out10[r]=m;
                unsigned ball=__ballot_sync(0xffffffffu, h==m);
                if(lane==(__ffs(ball)-1)) p++;
            }
            if(lane==0){
                #pragma unroll
                for(int r=0;r<10;r++) wtop[warp][r]=out10[r];
            }
        }
        __syncthreads();
        if(warp==0){
            int p=0; float s=0.f;
            #pragma unroll
            for(int r=0;r<10;r++){
                float h=(lane<8 && p<10)? wtop[lane][p] : -1e30f;
                float m=h;
                #pragma unroll
                for(int off=16;off;off>>=1)
                    m=fmaxf(m,__shfl_xor_sync(0xffffffffu,m,off));
                s+=m;
                unsigned ball=__ballot_sync(0xffffffffu, h==m && lane<8);
                if(lane==(__ffs(ball)-1)) p++;
            }
            if(lane==0){
                int dk=(int)s;
                if(dk<1)dk=1; if(dk>NN)dk=NN;
                s_dk=dk;
            }
        }
        __syncthreads();
        int dk=s_dk;
        #pragma unroll 2
        for(int i=tid;i<NN;i+=256){
            float myc=col[i];
            int r=0;
            #pragma unroll 4
            for(int k=0;k<NN;k++){
                float ck=col[k];
                r += (ck<myc) || (ck==myc && k<i);
            }
            if((r<dk) && sval[i]){
                atomicAdd(&g_mcnt[b*NN+i],1u);
                atomicMax(&g_mfirst[b*NN+i],(unsigned)(MM-j));
            }
        }
        {
            const float* gm=&gmask[(size_t)(b*MM+j)*(HM*HM)];
            float qx1=gx1*0.25f, qy1=gy1*0.25f, qx2=gx2*0.25f, qy2=gy2*0.25f;
            float gs=0.f;
            #pragma unroll
            for(int k=0;k<4;k++){
                int pix=tid+k*256;
                if(pix<TT*TT){
                    int ty=pix/TT, tx=pix%TT;
                    float ux=((float)tx+0.5f)/28.f, uy=((float)ty+0.5f)/28.f;
                    float Xg=qx1+(qx2-qx1)*ux-0.5f, Yg=qy1+(qy2-qy1)*uy-0.5f;
                    float gv=bilerp(gm,HM,HM,Xg,Yg);
                    g_gcrop[(size_t)(b*MM+j)*(TT*TT)+pix]=gv;
                    gs+=gv;
                }
            }
            #pragma unroll
            for(int off=16;off;off>>=1) gs+=__shfl_down_sync(0xffffffffu,gs,off);
            if(lane==0) sred[warp]=(double)gs;
            __syncthreads();
            if(tid==0){
                double t=0;
                #pragma unroll
                for(int w=0;w<8;w++) t+=sred[w];
                g_gsum[b*MM+j]=(float)t;
            }
        }
        return;
    }

    // ---- negative-class focal bulk ----
    {
        __shared__ double sred2[8];
        int base=(blk-PROJ_BLKS-COL_BLKS)*1280 + tid;
        double cl=0.0;
        #pragma unroll
        for(int k=0;k<5;k++){
            int e=base+k*256;
            float x=logits[e];
            float p=1.f/(1.f+__expf(-x));
            float sp=fmaxf(x,0.f)+log1pf(__expf(-fabsf(x)));
            cl += (double)(0.75f*p*p*sp);
        }
        #pragma unroll
        for(int off=16;off;off>>=1) cl+=__shfl_down_sync(0xffffffffu,cl,off);
        if(lane==0) sred2[warp]=cl;
        __syncthreads();
        if(tid==0){
            double a=0;
            #pragma unroll
            for(int w=0;w<8;w++) a+=sred2[w];
            atomicAdd(&g_accb[bank][0],a);
        }
    }
}

// ================= K2: atomics-resolved assignment + smem dice =================
__global__ void __launch_bounds__(256)
k_stage2(const float* __restrict__ logits, const float* __restrict__ boxes,
         const int* __restrict__ gcls, const float* __restrict__ gbox,
         float* __restrict__ out){
    int blk=blockIdx.x, tid=threadIdx.x;
    int lane=tid&31, warp=tid>>5;
    int bank=blk&31;
    int b=blk/(MM*2);
    int rem=blk%(MM*2);
    int j=rem>>1;
    int half=rem&1;

    __shared__ float pjs[HF*HF];    // 16 KB
    __shared__ float gcs[TT*TT];    // ~3 KB
    __shared__ int   lst[NN];
    __shared__ int   s_cnt;
    __shared__ float swy[8][TT];
    __shared__ int   sr0[8][TT], sr1[8][TT];
    if(tid==0) s_cnt=0;
    __syncthreads();

    // assignment: 3 coalesced loads per proposal
    {
        int t=tid;
        int i=2*t+half;
        if(t<150 && g_valid[b*NN+i]){
            unsigned cnt=__ldg(&g_mcnt[b*NN+i]);
            int gi;
            if(cnt==1u){
                gi=MM-(int)__ldg(&g_mfirst[b*NN+i]);
            } else {
                unsigned long long key=~__ldg(&g_amax[b*NN+i]);
                gi=(int)(key & 0xFFFFFFFFull);
            }
            if(gi==j){ int p=atomicAdd(&s_cnt,1); lst[p]=i; }
        }
    }
    __syncthreads();
    int cnt=s_cnt;

    if(cnt>0){
        {
            const float* pj=&g_proj[(size_t)(b*MM+j)*(HF*HF)];
            #pragma unroll
            for(int k=0;k<16;k++) pjs[k*256+tid]=pj[k*256+tid];
            const float* gc=&g_gcrop[(size_t)(b*MM+j)*(TT*TT)];
            #pragma unroll
            for(int k=0;k<4;k++){
                int p=tid+k*256;
                if(p<TT*TT) gcs[p]=gc[p];
            }
        }
        __syncthreads();

        for(int idx=warp; idx<cnt; idx+=8){
            int i=lst[idx];
            const float* bx=&boxes[(size_t)(b*NN+i)*4];
            const float FS=(float)(64.0/896.0);
            float px1=bx[0]*FS, py1=bx[1]*FS, px2=bx[2]*FS, py2=bx[3]*FS;

            float u=((float)lane+0.5f)*(1.f/28.f);
            float X=px1+(px2-px1)*u-0.5f;
            float x0f=fminf(fmaxf(floorf(X),0.f),63.f);
            float wx=fminf(fmaxf(X-x0f,0.f),1.f);
            int x0=(int)x0f;
            int x1=min(x0+1,63);
            float Y=py1+(py2-py1)*u-0.5f;
            float y0f=fminf(fmaxf(floorf(Y),0.f),63.f);
            float wyv=fminf(fmaxf(Y-y0f,0.f),1.f);
            int r0=((int)y0f)*HF;
            int r1=min((int)y0f+1,63)*HF;
            if(lane<TT){ swy[warp][lane]=wyv; sr0[warp][lane]=r0; sr1[warp][lane]=r1; }
            __syncwarp();

            float inter=0.f, sm=0.f;
            #pragma unroll
            for(int r=0;r<TT;r++){
                float wyr=swy[warp][r];
                int ro0=sr0[warp][r], ro1=sr1[warp][r];
                if(lane<TT){
                    float g00=pjs[ro0+x0], g01=pjs[ro0+x1];
                    float g10=pjs[ro1+x0], g11=pjs[ro1+x1];
                    float top=g00+wx*(g01-g00);
                    float bot=g10+wx*(g11-g10);
                    float z=top+wyr*(bot-top);
                    float mv=__fdividef(1.f, 1.f+__expf(-z));
                    inter+=mv*gcs[r*TT+lane]; sm+=mv;
                }
            }
            __syncwarp();
            #pragma unroll
            for(int off=16;off;off>>=1){
                inter+=__shfl_down_sync(0xffffffffu,inter,off);
                sm   +=__shfl_down_sync(0xffffffffu,sm,off);
            }
            if(lane==0){
                float sgv=g_gsum[b*MM+j];
                double dice=(double)(1.f-2.f*inter/(sm+sgv+EPSF));
                const float* gb=&gbox[(size_t)(b*MM+j)*4];
                float na0=bx[0]/S_IMG,na1=bx[1]/S_IMG,na2=bx[2]/S_IMG,na3=bx[3]/S_IMG;
                float ng0=gb[0]/S_IMG,ng1=gb[1]/S_IMG,ng2=gb[2]/S_IMG,ng3=gb[3]/S_IMG;
                double l1=(double)(fabsf(na0-ng0)+fabsf(na1-ng1)+fabsf(na2-ng2)+fabsf(na3-ng3));
                double gl=(double)(1.f-giou_pair(na0,na1,na2,na3,ng0,ng1,ng2,ng3));
                int mcls=gcls[b*MM+j];
                float x=logits[(size_t)(b*NN+i)*CC+mcls];
                float p=1.f/(1.f+expf(-x));
                float sp=fmaxf(x,0.f)+log1pf(expf(-fabsf(x)));
                float posv=0.25f*(1.f-p)*(1.f-p)*(sp-x);
                float negv=0.75f*p*p*sp;
                atomicAdd(&g_accb[bank][0],(double)(posv-negv));
                atomicAdd(&g_accb[bank][1],l1);
                atomicAdd(&g_accb[bank][2],gl);
                atomicAdd(&g_accb[bank][3],dice);
                atomicAdd(&g_accb[bank][4],1.0);
            }
        }
    }

    // ---- ticket: last finished block finalizes + resets all replay state ----
    __shared__ int amlast;
    __syncthreads();
    __threadfence();
    if(tid==0){
        int t=atomicAdd(&g_done,1);
        amlast=(t==(int)gridDim.x-1);
    }
    __syncthreads();
    if(amlast){
        __threadfence();
        // block-wide reset of assignment atomics for next graph replay
        for(int i=tid;i<BB*NN;i+=256){
            g_amax[i]=0ull;
            g_mcnt[i]=0u;
            g_mfirst[i]=0u;
        }
        if(tid==0){
            double a0=0,a1=0,a2=0,a3=0,a4=0;
            #pragma unroll
            for(int k=0;k<32;k++){
                a0+=g_accb[k][0]; a1+=g_accb[k][1]; a2+=g_accb[k][2];
                a3+=g_accb[k][3]; a4+=g_accb[k][4];
                g_accb[k][0]=0.0; g_accb[k][1]=0.0; g_accb[k][2]=0.0;
                g_accb[k][3]=0.0; g_accb[k][4]=0.0;
            }
            out[0]=(float)(2.0*a0/a4);
            out[1]=(float)(5.0*a1/a4);
            out[2]=(float)(2.0*a2/a4);
            out[3]=(float)(5.0*a3/a4);
            g_done=0;
        }
    }
}

extern "C" void kernel_launch(void* const* d_in, const int* in_sizes, int n_in,
                              void* d_out, int out_size){
    const float* logits=(const float*)d_in[0];
    const float* boxes =(const float*)d_in[1];
    const float* feat  =(const float*)d_in[2];
    const float* wmask =(const float*)d_in[3];
    const int*   gcls  =(const int*)  d_in[4];
    const float* gbox  =(const float*)d_in[5];
    const float* gmask =(const float*)d_in[6];
    float* out=(float*)d_out;

    k_stage1<<<K1_GRID,256>>>(logits,boxes,feat,wmask,gcls,gbox,gmask);
    k_stage2<<<K2_GRID,256>>>(logits,boxes,gcls,gbox,out);
}

// round 17
// speedup vs baseline: 1.0219x; 1.0075x over previous
#include <cuda_runtime.h>
#include <math.h>

#define BB 4
#define NN 300
#define CC 80
#define MM 24
#define CF 128
#define HF 64
#define HM 224
#define TT 28

#define S_IMG 896.0f
#define CENTER_R 44.8f
#define EPSF 1e-8f

#define PROJ_BLKS  128                      // 4 img * 16 chunks * 2 class-groups(12)
#define COL_BLKS   (BB*MM)                  // 96
#define NEG_BLKS   75                       // 75*1280 = 96000
#define K1_GRID    (PROJ_BLKS+COL_BLKS+NEG_BLKS)   // 299
#define K2_GRID    (BB*MM)                  // 96: block per (b, j), 512 threads

// ---------------- scratch ----------------
__device__ float  g_proj[BB*MM*HF*HF];
__device__ int    g_valid[BB*NN];
__device__ unsigned long long g_amax[BB*NN] = {};   // ~min-key (argmin via atomicMax)
__device__ unsigned g_mcnt[BB*NN] = {};             // match count
__device__ unsigned g_mfirst[BB*NN] = {};           // MM - first_matched_j (0 = none)
__device__ float  g_gcrop[BB*MM*TT*TT];
__device__ float  g_gsum[BB*MM];
__device__ double g_accb[32][5] = {};
__device__ int    g_done = 0;

// ---------------- helpers ----------------
__device__ __forceinline__ float sigm(float x){ return 1.f/(1.f+expf(-x)); }

__device__ __forceinline__ float iou_exact(float ax1,float ay1,float ax2,float ay2,
                                           float bx1,float by1,float bx2,float by2){
    float ltx=fmaxf(ax1,bx1), lty=fmaxf(ay1,by1);
    float rbx=fminf(ax2,bx2), rby=fminf(ay2,by2);
    float w=fmaxf(__fsub_rn(rbx,ltx),0.f), h=fmaxf(__fsub_rn(rby,lty),0.f);
    float inter=__fmul_rn(w,h);
    float aA=__fmul_rn(fmaxf(__fsub_rn(ax2,ax1),0.f), fmaxf(__fsub_rn(ay2,ay1),0.f));
    float aB=__fmul_rn(fmaxf(__fsub_rn(bx2,bx1),0.f), fmaxf(__fsub_rn(by2,by1),0.f));
    float uni=__fsub_rn(__fadd_rn(aA,aB), inter);
    return __fdiv_rn(inter, __fadd_rn(uni, EPSF));
}

__device__ __forceinline__ float giou_pair(float a0,float a1,float a2,float a3,
                                           float g0,float g1,float g2,float g3){
    float ltx=fmaxf(a0,g0), lty=fmaxf(a1,g1);
    float rbx=fminf(a2,g2), rby=fminf(a3,g3);
    float w=fmaxf(rbx-ltx,0.f), h=fmaxf(rby-lty,0.f);
    float inter=w*h;
    float aA=fmaxf(a2-a0,0.f)*fmaxf(a3-a1,0.f);
    float aB=fmaxf(g2-g0,0.f)*fmaxf(g3-g1,0.f);
    float uni=aA+aB-inter;
    float iou=inter/(uni+EPSF);
    float ex=fminf(a0,g0), ey=fminf(a1,g1);
    float fx=fmaxf(a2,g2), fy=fmaxf(a3,g3);
    float enc=fmaxf(fx-ex,0.f)*fmaxf(fy-ey,0.f);
    return iou-(enc-uni)/(enc+EPSF);
}

__device__ __forceinline__ float bilerp(const float* __restrict__ img,int W,int H,float X,float Y){
    float x0f=fminf(fmaxf(floorf(X),0.f),(float)(W-1));
    float y0f=fminf(fmaxf(floorf(Y),0.f),(float)(H-1));
    float wx=fminf(fmaxf(X-x0f,0.f),1.f);
    float wy=fminf(fmaxf(Y-y0f,0.f),1.f);
    int x0=(int)x0f, y0=(int)y0f;
    int x1=min(x0+1,W-1), y1=min(y0+1,H-1);
    float g00=__ldg(&img[y0*W+x0]), g01=__ldg(&img[y0*W+x1]);
    float g10=__ldg(&img[y1*W+x0]), g11=__ldg(&img[y1*W+x1]);
    return g00*(1.f-wx)*(1.f-wy)+g01*wx*(1.f-wy)+g10*(1.f-wx)*wy+g11*wx*wy;
}

// ordered-uint encoding: strictly monotonic with float order
__device__ __forceinline__ unsigned float_ord(float f){
    unsigned u=__float_as_uint(f);
    return (u&0x80000000u)? ~u : (u|0x80000000u);
}

// ================= K1: proj (register-buffered) || columns || neg focal =================
__global__ void __launch_bounds__(256)
k_stage1(const float* __restrict__ logits, const float* __restrict__ boxes,
         const float* __restrict__ feat,   const float* __restrict__ wmask,
         const int*   __restrict__ gcls,   const float* __restrict__ gbox,
         const float* __restrict__ gmask){
    int blk=blockIdx.x, tid=threadIdx.x;
    int lane=tid&31, warp=tid>>5;
    int bank=blk&31;

    if(blk < PROJ_BLKS){
        __shared__ float wm[12*CF];
        int b=blk/32;
        int r=blk%32;
        int chunk=r>>1;
        int jg=r&1;
        int px0=chunk*256;
        for(int idx=tid; idx<12*CF; idx+=256){
            int j=jg*12+idx/CF, f=idx%CF;
            wm[idx]=wmask[gcls[b*MM+j]*CF+f];
        }
        __syncthreads();
        float acc[12];
        #pragma unroll
        for(int j=0;j<12;j++) acc[j]=0.f;
        const float* fb = feat + ((size_t)b*CF)*(HF*HF) + px0 + tid;
        for(int fc=0; fc<8; fc++){
            float v[16];
            #pragma unroll
            for(int k=0;k<16;k++)
                v[k]=__ldg(&fb[(size_t)(fc*16+k)*(HF*HF)]);
            #pragma unroll
            for(int k=0;k<16;k++){
                const float* w0=&wm[fc*16+k];
                #pragma unroll
                for(int j=0;j<12;j++) acc[j] += v[k]*w0[j*CF];
            }
        }
        #pragma unroll
        for(int j=0;j<12;j++) g_proj[((b*MM+jg*12+j)*(HF*HF))+px0+tid]=acc[j];
        return;
    }

    if(blk < PROJ_BLKS+COL_BLKS){
        int idx=blk-PROJ_BLKS;
        int b=idx/MM, j=idx%MM;
        __shared__ float col[NN];
        __shared__ unsigned char sval[NN];
        __shared__ float sg[MM][4];
        __shared__ float wtop[8][10];
        __shared__ int   s_dk;
        __shared__ double sred[8];
        if(tid<MM){
            sg[tid][0]=gbox[(b*MM+tid)*4+0]; sg[tid][1]=gbox[(b*MM+tid)*4+1];
            sg[tid][2]=gbox[(b*MM+tid)*4+2]; sg[tid][3]=gbox[(b*MM+tid)*4+3];
        }
        __syncthreads();
        float gx1=sg[j][0],gy1=sg[j][1],gx2=sg[j][2],gy2=sg[j][3];
        float gcx=(gx1+gx2)*0.5f, gcy=(gy1+gy2)*0.5f;
        int cls_j=gcls[b*MM+j];
        float ng0=gx1/S_IMG,ng1=gy1/S_IMG,ng2=gx2/S_IMG,ng3=gy2/S_IMG;
        float loc[10];
        #pragma unroll
        for(int k=0;k<10;k++) loc[k]=-1e30f;
        #pragma unroll 2
        for(int i=tid;i<NN;i+=256){
            const float* bx=&boxes[(size_t)(b*NN+i)*4];
            float ax1=bx[0],ay1=bx[1],ax2=bx[2],ay2=bx[3];
            float cx=(ax1+ax2)*0.5f, cy=(ay1+ay2)*0.5f;
            int any=0;
            #pragma unroll 4
            for(int q=0;q<MM;q++){
                float qx1=sg[q][0],qy1=sg[q][1],qx2=sg[q][2],qy2=sg[q][3];
                bool igt=(cx>=qx1)&&(cx<=qx2)&&(cy>=qy1)&&(cy<=qy2);
                bool ict=(fabsf(cx-(qx1+qx2)*0.5f)<=CENTER_R)&&(fabsf(cy-(qy1+qy2)*0.5f)<=CENTER_R);
                any |= (igt||ict);
            }
            sval[i]=(unsigned char)any;
            g_valid[b*NN+i]=any;
            float x=logits[(size_t)(b*NN+i)*CC + cls_j];
            float p=sigm(x);
            float neg=-logf(1.f-p+EPSF)*0.75f*p*p;
            float pos=-logf(p+EPSF)*0.25f*(1.f-p)*(1.f-p);
            float cls_cost=2.f*(pos-neg);
            float na0=ax1/S_IMG,na1=ay1/S_IMG,na2=ax2/S_IMG,na3=ay2/S_IMG;
            float l1c=5.f*(fabsf(na0-ng0)+fabsf(na1-ng1)+fabsf(na2-ng2)+fabsf(na3-ng3));
            float ngiou=giou_pair(na0,na1,na2,na3,ng0,ng1,ng2,ng3);
            bool ingt=(cx>=gx1)&&(cx<=gx2)&&(cy>=gy1)&&(cy<=gy2);
            bool inct=(fabsf(cx-gcx)<=CENTER_R)&&(fabsf(cy-gcy)<=CENTER_R);
            float cost=cls_cost+l1c+2.f*(1.f-ngiou);
            cost += (ingt&&inct)?0.f:1e5f;
            cost += any?0.f:1e9f;
            col[i]=cost;
            if(any){
                unsigned long long key=(((unsigned long long)float_ord(cost))<<32)|(unsigned)j;
                atomicMax(&g_amax[b*NN+i], ~key);
            }
            float iou=iou_exact(ax1,ay1,ax2,ay2,gx1,gy1,gx2,gy2);
            float v=any? iou : 0.f;
            if(v>loc[9]){
                int k=9;
                #pragma unroll
                for(int q=9;q>0;q--){
                    if(loc[q-1]<v){ loc[q]=loc[q-1]; k=q-1; } else break;
                }
                loc[k]=v;
            }
        }
        {
            int p=0; float out10[10];
            #pragma unroll
            for(int r=0;r<10;r++){
                float h=(p<10)?loc[p]:-1e30f;
                float m=h;
                #pragma unroll
                for(int off=16;off;off>>=1)
                    m=fmaxf(m,__shfl_xor_sync(0xffffffffu,m,off));
                out10[r]=m;
                unsigned ball=__ballot_sync(0xffffffffu, h==m);
                if(lane==(__ffs(ball)-1)) p++;
            }
            if(lane==0){
                #pragma unroll
                for(int r=0;r<10;r++) wtop[warp][r]=out10[r];
            }
        }
        __syncthreads();
        if(warp==0){
            int p=0; float s=0.f;
            #pragma unroll
            for(int r=0;r<10;r++){
                float h=(lane<8 && p<10)? wtop[lane][p] : -1e30f;
                float m=h;
                #pragma unroll
                for(int off=16;off;off>>=1)
                    m=fmaxf(m,__shfl_xor_sync(0xffffffffu,m,off));
                s+=m;
                unsigned ball=__ballot_sync(0xffffffffu, h==m && lane<8);
                if(lane==(__ffs(ball)-1)) p++;
            }
            if(lane==0){
                int dk=(int)s;
                if(dk<1)dk=1; if(dk>NN)dk=NN;
                s_dk=dk;
            }
        }
        __syncthreads();
        int dk=s_dk;
        #pragma unroll 2
        for(int i=tid;i<NN;i+=256){
            float myc=col[i];
            int r=0;
            #pragma unroll 4
            for(int k=0;k<NN;k++){
                float ck=col[k];
                r += (ck<myc) || (ck==myc && k<i);
            }
            if((r<dk) && sval[i]){
                atomicAdd(&g_mcnt[b*NN+i],1u);
                atomicMax(&g_mfirst[b*NN+i],(unsigned)(MM-j));
            }
        }
        {
            const float* gm=&gmask[(size_t)(b*MM+j)*(HM*HM)];
            float qx1=gx1*0.25f, qy1=gy1*0.25f, qx2=gx2*0.25f, qy2=gy2*0.25f;
            float gs=0.f;
            #pragma unroll
            for(int k=0;k<4;k++){
                int pix=tid+k*256;
                if(pix<TT*TT){
                    int ty=pix/TT, tx=pix%TT;
                    float ux=((float)tx+0.5f)/28.f, uy=((float)ty+0.5f)/28.f;
                    float Xg=qx1+(qx2-qx1)*ux-0.5f, Yg=qy1+(qy2-qy1)*uy-0.5f;
                    float gv=bilerp(gm,HM,HM,Xg,Yg);
                    g_gcrop[(size_t)(b*MM+j)*(TT*TT)+pix]=gv;
                    gs+=gv;
                }
            }
            #pragma unroll
            for(int off=16;off;off>>=1) gs+=__shfl_down_sync(0xffffffffu,gs,off);
            if(lane==0) sred[warp]=(double)gs;
            __syncthreads();
            if(tid==0){
                double t=0;
                #pragma unroll
                for(int w=0;w<8;w++) t+=sred[w];
                g_gsum[b*MM+j]=(float)t;
            }
        }
        return;
    }

    // ---- negative-class focal bulk ----
    {
        __shared__ double sred2[8];
        int base=(blk-PROJ_BLKS-COL_BLKS)*1280 + tid;
        double cl=0.0;
        #pragma unroll
        for(int k=0;k<5;k++){
            int e=base+k*256;
            float x=logits[e];
            float p=1.f/(1.f+__expf(-x));
            float sp=fmaxf(x,0.f)+log1pf(__expf(-fabsf(x)));
            cl += (double)(0.75f*p*p*sp);
        }
        #pragma unroll
        for(int off=16;off;off>>=1) cl+=__shfl_down_sync(0xffffffffu,cl,off);
        if(lane==0) sred2[warp]=cl;
        __syncthreads();
        if(tid==0){
            double a=0;
            #pragma unroll
            for(int w=0;w<8;w++) a+=sred2[w];
            atomicAdd(&g_accb[bank][0],a);
        }
    }
}

// ================= K2: 96 blocks x 512 threads; atomics-resolved assignment + smem dice =================
__global__ void __launch_bounds__(512)
k_stage2(const float* __restrict__ logits, const float* __restrict__ boxes,
         const int* __restrict__ gcls, const float* __restrict__ gbox,
         float* __restrict__ out){
    int blk=blockIdx.x, tid=threadIdx.x;
    int lane=tid&31, warp=tid>>5;      // 16 warps
    int bank=blk&31;
    int b=blk/MM;
    int j=blk%MM;

    __shared__ float pjs[HF*HF];    // 16 KB
    __shared__ float gcs[TT*TT];    // ~3 KB
    __shared__ int   lst[NN];
    __shared__ int   s_cnt;
    __shared__ float swy[16][TT];
    __shared__ int   sr0[16][TT], sr1[16][TT];
    if(tid==0) s_cnt=0;
    __syncthreads();

    // assignment: 1 proposal per thread (512 >= 300), 3 coalesced loads
    {
        int i=tid;
        if(i<NN && g_valid[b*NN+i]){
            unsigned cnt=__ldg(&g_mcnt[b*NN+i]);
            int gi;
            if(cnt==1u){
                gi=MM-(int)__ldg(&g_mfirst[b*NN+i]);
            } else {
                unsigned long long key=~__ldg(&g_amax[b*NN+i]);
                gi=(int)(key & 0xFFFFFFFFull);
            }
            if(gi==j){ int p=atomicAdd(&s_cnt,1); lst[p]=i; }
        }
    }
    __syncthreads();
    int cnt=s_cnt;

    if(cnt>0){
        {
            const float* pj=&g_proj[(size_t)(b*MM+j)*(HF*HF)];
            #pragma unroll
            for(int k=0;k<8;k++) pjs[k*512+tid]=pj[k*512+tid];
            const float* gc=&g_gcrop[(size_t)(b*MM+j)*(TT*TT)];
            #pragma unroll
            for(int k=0;k<2;k++){
                int p=tid+k*512;
                if(p<TT*TT) gcs[p]=gc[p];
            }
        }
        __syncthreads();

        for(int idx=warp; idx<cnt; idx+=16){
            int i=lst[idx];
            const float* bx=&boxes[(size_t)(b*NN+i)*4];
            const float FS=(float)(64.0/896.0);
            float px1=bx[0]*FS, py1=bx[1]*FS, px2=bx[2]*FS, py2=bx[3]*FS;

            float u=((float)lane+0.5f)*(1.f/28.f);
            float X=px1+(px2-px1)*u-0.5f;
            float x0f=fminf(fmaxf(floorf(X),0.f),63.f);
            float wx=fminf(fmaxf(X-x0f,0.f),1.f);
            int x0=(int)x0f;
            int x1=min(x0+1,63);
            float Y=py1+(py2-py1)*u-0.5f;
            float y0f=fminf(fmaxf(floorf(Y),0.f),63.f);
            float wyv=fminf(fmaxf(Y-y0f,0.f),1.f);
            int r0=((int)y0f)*HF;
            int r1=min((int)y0f+1,63)*HF;
            if(lane<TT){ swy[warp][lane]=wyv; sr0[warp][lane]=r0; sr1[warp][lane]=r1; }
            __syncwarp();

            float inter=0.f, sm=0.f;
            #pragma unroll
            for(int r=0;r<TT;r++){
                float wyr=swy[warp][r];
                int ro0=sr0[warp][r], ro1=sr1[warp][r];
                if(lane<TT){
                    float g00=pjs[ro0+x0], g01=pjs[ro0+x1];
                    float g10=pjs[ro1+x0], g11=pjs[ro1+x1];
                    float top=g00+wx*(g01-g00);
                    float bot=g10+wx*(g11-g10);
                    float z=top+wyr*(bot-top);
                    float mv=__fdividef(1.f, 1.f+__expf(-z));
                    inter+=mv*gcs[r*TT+lane]; sm+=mv;
                }
            }
            __syncwarp();
            #pragma unroll
            for(int off=16;off;off>>=1){
                inter+=__shfl_down_sync(0xffffffffu,inter,off);
                sm   +=__shfl_down_sync(0xffffffffu,sm,off);
            }
            if(lane==0){
                float sgv=g_gsum[b*MM+j];
                double dice=(double)(1.f-2.f*inter/(sm+sgv+EPSF));
                const float* gb=&gbox[(size_t)(b*MM+j)*4];
                float na0=bx[0]/S_IMG,na1=bx[1]/S_IMG,na2=bx[2]/S_IMG,na3=bx[3]/S_IMG;
                float ng0=gb[0]/S_IMG,ng1=gb[1]/S_IMG,ng2=gb[2]/S_IMG,ng3=gb[3]/S_IMG;
                double l1=(double)(fabsf(na0-ng0)+fabsf(na1-ng1)+fabsf(na2-ng2)+fabsf(na3-ng3));
                double gl=(double)(1.f-giou_pair(na0,na1,na2,na3,ng0,ng1,ng2,ng3));
                int mcls=gcls[b*MM+j];
                float x=logits[(size_t)(b*NN+i)*CC+mcls];
                float p=1.f/(1.f+expf(-x));
                float sp=fmaxf(x,0.f)+log1pf(expf(-fabsf(x)));
                float posv=0.25f*(1.f-p)*(1.f-p)*(sp-x);
                float negv=0.75f*p*p*sp;
                atomicAdd(&g_accb[bank][0],(double)(posv-negv));
                atomicAdd(&g_accb[bank][1],l1);
                atomicAdd(&g_accb[bank][2],gl);
                atomicAdd(&g_accb[bank][3],dice);
                atomicAdd(&g_accb[bank][4],1.0);
            }
        }
    }

    // ---- ticket: last finished block finalizes + resets all replay state ----
    __shared__ int amlast;
    __syncthreads();
    __threadfence();
    if(tid==0){
        int t=atomicAdd(&g_done,1);
        amlast=(t==(int)gridDim.x-1);
    }
    __syncthreads();
    if(amlast){
        __threadfence();
        for(int i=tid;i<BB*NN;i+=512){
            g_amax[i]=0ull;
            g_mcnt[i]=0u;
            g_mfirst[i]=0u;
        }
        if(tid==0){
            double a0=0,a1=0,a2=0,a3=0,a4=0;
            #pragma unroll
            for(int k=0;k<32;k++){
                a0+=g_accb[k][0]; a1+=g_accb[k][1]; a2+=g_accb[k][2];
                a3+=g_accb[k][3]; a4+=g_accb[k][4];
                g_accb[k][0]=0.0; g_accb[k][1]=0.0; g_accb[k][2]=0.0;
                g_accb[k][3]=0.0; g_accb[k][4]=0.0;
            }
            out[0]=(float)(2.0*a0/a4);
            out[1]=(float)(5.0*a1/a4);
            out[2]=(float)(2.0*a2/a4);
            out[3]=(float)(5.0*a3/a4);
            g_done=0;
        }
    }
}

extern "C" void kernel_launch(void* const* d_in, const int* in_sizes, int n_in,
                              void* d_out, int out_size){
    const float* logits=(const float*)d_in[0];
    const float* boxes =(const float*)d_in[1];
    const float* feat  =(const float*)d_in[2];
    const float* wmask =(const float*)d_in[3];
    const int*   gcls  =(const int*)  d_in[4];
    const float* gbox  =(const float*)d_in[5];
    const float* gmask =(const float*)d_in[6];
    float* out=(float*)d_out;

    k_stage1<<<K1_GRID,256>>>(logits,boxes,feat,wmask,gcls,gbox,gmask);
    k_stage2<<<K2_GRID,512>>>(logits,boxes,gcls,gbox,out);
}